// round 15
// baseline (speedup 1.0000x reference)
#include <cuda_runtime.h>

#define NANCH 19200      // 3*80*80 anchors per image
#define NIMG  8
#define MTGT  100
#define QN    25                            // targets per quarter
#define NCLS  80
#define THREADS 256
#define NWARP (THREADS / 32)                // 8
#define SLOTS 64                            // anchor slots per block
#define APT 2
#define ANCH_PER_BLK (SLOTS * APT)          // 128
#define NBLK_PER_IMG (NANCH / ANCH_PER_BLK) // 150
#define NBLOCKS (NIMG * NBLK_PER_IMG)       // 1200

#define LN2F   0.6931471805599453f
#define C_FALSE (0.75f * LN2F)

__device__ float4   g_part[NBLOCKS];
__device__ unsigned g_count;

__device__ __forceinline__ float frcp_approx(float x) {
    float r;
    asm("rcp.approx.f32 %0, %1;" : "=f"(r) : "f"(x));
    return r;
}

// non-target focal term / C_FALSE:  p^2 * lg2(Q),  Q=1+exp(x), p=1-rcp(Q)
__device__ __forceinline__ float false_core(float x) {
    float Q = 1.0f + __expf(x);
    float R = frcp_approx(Q);
    float L = __log2f(Q);
    float p = 1.0f - R;
    return p * p * L;
}

__device__ __forceinline__ float false4(float4 v) {
    return false_core(v.x) + false_core(v.y) + false_core(v.z) + false_core(v.w);
}

__global__ void __launch_bounds__(THREADS, 8) loss_fused(
    const float* __restrict__ obj,    // [8,19200]
    const float* __restrict__ boxes,  // [8,19200,4] (cx,cy,w,h)
    const float* __restrict__ cls,    // [8,19200,80]
    const float* __restrict__ tbox,   // [8,100,4]
    const int*   __restrict__ tlab,   // [8,100]
    float*       __restrict__ out)
{
    __shared__ float4 s_lohi[MTGT];          // lox,loy,hix,hiy
    __shared__ float  s_area[MTGT];
    __shared__ int    s_lab[MTGT];
    __shared__ int    s_vm[4][SLOTS][APT];   // packed argmax per target-quarter
    __shared__ int    s_pos_rowb4[ANCH_PER_BLK]; // row*20 (float4 index)
    __shared__ int    s_pos_rt[ANCH_PER_BLK];    // (row<<7) | tgt
    __shared__ int    s_pos_lab[ANCH_PER_BLK];
    __shared__ int    s_wtot[4];
    __shared__ float  s_red[NWARP][4];
    __shared__ float  s_img[NIMG][4];
    __shared__ unsigned s_is_last;

    const int tid  = threadIdx.x;
    const int lane = tid & 31;
    const int wid  = tid >> 5;
    const int slot = tid & (SLOTS - 1);            // 0..63
    const int q    = tid >> 6;                     // quarter 0..3
    const int img  = blockIdx.x / NBLK_PER_IMG;
    const int ablk = blockIdx.x % NBLK_PER_IMG;
    const int bbase = img * NANCH + ablk * ANCH_PER_BLK;
    const int base  = bbase + slot * APT;

    // ── Targets to shared ──
    if (tid < MTGT) {
        float4 tb = ((const float4*)tbox)[img * MTGT + tid];
        s_lohi[tid] = make_float4(tb.x - 0.5f * tb.z, tb.y - 0.5f * tb.w,
                                  tb.x + 0.5f * tb.z, tb.y + 0.5f * tb.w);
        s_area[tid] = tb.z * tb.w;
        s_lab[tid]  = tlab[img * MTGT + tid];
    }
    __syncthreads();

    // ── Load this slot's 2 anchors ──
    float lo1x[APT], lo1y[APT], hi1x[APT], hi1y[APT], a1[APT];
    int   vmax[APT];
    #pragma unroll
    for (int a = 0; a < APT; a++) {
        float4 bxv = ((const float4*)boxes)[base + a];
        lo1x[a] = bxv.x - 0.5f * bxv.z;  lo1y[a] = bxv.y - 0.5f * bxv.w;
        hi1x[a] = bxv.x + 0.5f * bxv.z;  hi1y[a] = bxv.y + 0.5f * bxv.w;
        a1[a]   = bxv.z * bxv.w;
        vmax[a] = -1;
    }

    // ── Packed argmax of x = inter/(a1+ta) over this quarter's 25 targets ──
    const int m0 = q * QN;
    #pragma unroll 5
    for (int mm = 0; mm < QN; mm++) {
        int m = m0 + mm;
        float4 t  = s_lohi[m];
        float  ta = s_area[m];
        int idxbits = 127 - m;
        #pragma unroll
        for (int a = 0; a < APT; a++) {
            float wx = fminf(hi1x[a], t.z) - fmaxf(lo1x[a], t.x);    // unclamped
            float wy = fmaxf(fminf(hi1y[a], t.w) - fmaxf(lo1y[a], t.y), 0.0f);
            float inter = wx * wy;
            float x  = inter * frcp_approx(a1[a] + ta);
            int pk = (__float_as_int(x) & (int)0xFFFFFF80) | idxbits;
            vmax[a] = max(vmax[a], pk);
        }
    }
    s_vm[q][slot][0] = vmax[0];
    s_vm[q][slot][1] = vmax[1];
    __syncthreads();

    // ── Merge quarters: one anchor per thread (tid < 128), positivity, BCE ──
    bool  pos = false;
    float bce = 0.0f, posf = 0.0f;
    int   bidx = 0, arow = 0;
    if (tid < ANCH_PER_BLK) {
        int aslot = tid >> 1;
        int aj    = tid & 1;
        arow = bbase + tid;
        int v = max(max(s_vm[0][aslot][aj], s_vm[1][aslot][aj]),
                    max(s_vm[2][aslot][aj], s_vm[3][aslot][aj]));
        bidx = 127 - (v & 127);
        float4 bxv = ((const float4*)boxes)[arow];          // L1-hot
        float alox = bxv.x - 0.5f * bxv.z, aloy = bxv.y - 0.5f * bxv.w;
        float ahix = bxv.x + 0.5f * bxv.z, ahiy = bxv.y + 0.5f * bxv.w;
        float aa   = bxv.z * bxv.w;
        float4 t = s_lohi[bidx];
        float wx = fmaxf(fminf(ahix, t.z) - fmaxf(alox, t.x), 0.0f);
        float wy = fmaxf(fminf(ahiy, t.w) - fmaxf(aloy, t.y), 0.0f);
        pos = (3.0f * (wx * wy) >= aa + s_area[bidx] + 1e-6f);
        posf = pos ? 1.0f : 0.0f;
        float o = obj[arow];
        bce = -fmaxf(__logf(pos ? o : 1.0f - o), -100.0f);
    }

    // ── Deterministic compaction (anchor order) via ballot ──
    unsigned ball = __ballot_sync(0xFFFFFFFFu, pos);
    if (lane == 0 && wid < 4) s_wtot[wid] = __popc(ball);
    __syncthreads();
    int P = 0, wbase = 0;
    #pragma unroll
    for (int w = 0; w < 4; w++) {
        P += s_wtot[w];
        wbase += (w < wid) ? s_wtot[w] : 0;
    }
    if (pos) {
        int ofs = wbase + __popc(ball & ((1u << lane) - 1u));
        s_pos_rowb4[ofs] = arow * (NCLS / 4);
        s_pos_rt[ofs]    = (arow << 7) | bidx;
        s_pos_lab[ofs]   = s_lab[bidx];
    }
    __syncthreads();

    // ── Per-positive pass: GIoU + focal label-column correction (fused) ──
    float bbox = 0.0f;
    float fl = 0.0f;
    for (int i = tid; i < P; i += THREADS) {
        int rt = s_pos_rt[i];
        int prow = rt >> 7;
        int bm   = rt & 127;
        float4 pb = ((const float4*)boxes)[prow];   // L1-hot
        float plox = pb.x - 0.5f * pb.z, ploy = pb.y - 0.5f * pb.w;
        float phix = pb.x + 0.5f * pb.z, phiy = pb.y + 0.5f * pb.w;
        float pa   = pb.z * pb.w;
        float4 t = s_lohi[bm];
        float wx = fmaxf(fminf(phix, t.z) - fmaxf(plox, t.x), 0.0f);
        float wy = fmaxf(fminf(phiy, t.w) - fmaxf(ploy, t.y), 0.0f);
        float inter = wx * wy;
        float uni = pa + s_area[bm] - inter;
        float iou = __fdividef(inter, uni + 1e-6f);
        float ex = fmaxf(fmaxf(phix, t.z) - fminf(plox, t.x), 0.0f);
        float ey = fmaxf(fmaxf(phiy, t.w) - fminf(ploy, t.y), 0.0f);
        float enc = ex * ey;
        bbox += 1.0f - (iou - __fdividef(enc - uni, enc + 1e-6f));

        // label-column focal correction: + true_term − false_term
        float x = cls[s_pos_rowb4[i] * 4 + s_pos_lab[i]];
        float Q = 1.0f + __expf(x);
        float R = frcp_approx(Q);
        float L = __log2f(Q);
        float p = 1.0f - R;
        float falseT = C_FALSE * (p * p * L);
        float trueT  = 0.25f * (R * R) * (LN2F * L - x);
        fl += trueT - falseT;
    }

    // ── Focal main loop: float4-vectorized false formula over all 80 cols ──
    {
        const float4* cls4 = (const float4*)cls;
        const int items = P * (NCLS / 4);           // 20 vec-items per positive
        int i = tid;
        for (; i + THREADS < items; i += 2 * THREADS) {
            unsigned i0 = i, i1 = i + THREADS;
            unsigned a0 = i0 / 20u, a1i = i1 / 20u;
            int c0 = i0 - a0 * 20u, c1 = i1 - a1i * 20u;
            float4 v0 = cls4[s_pos_rowb4[a0] + c0];
            float4 v1 = cls4[s_pos_rowb4[a1i] + c1];
            fl = fmaf(false4(v0) + false4(v1), C_FALSE, fl);
        }
        if (i < items) {
            unsigned a = (unsigned)i / 20u;
            int cc = i - a * 20u;
            fl = fmaf(false4(cls4[s_pos_rowb4[a] + cc]), C_FALSE, fl);
        }
    }

    // ── single-sync fused block reduction of (bce, posf, bbox, fl) ──
    float v0 = bce, v1 = posf, v2 = bbox, v3 = fl;
    #pragma unroll
    for (int off = 16; off > 0; off >>= 1) {
        v0 += __shfl_down_sync(0xFFFFFFFFu, v0, off);
        v1 += __shfl_down_sync(0xFFFFFFFFu, v1, off);
        v2 += __shfl_down_sync(0xFFFFFFFFu, v2, off);
        v3 += __shfl_down_sync(0xFFFFFFFFu, v3, off);
    }
    if (lane == 0) {
        s_red[wid][0] = v0; s_red[wid][1] = v1;
        s_red[wid][2] = v2; s_red[wid][3] = v3;
    }
    __syncthreads();
    if (tid == 0) {
        float r0 = 0, r1 = 0, r2 = 0, r3 = 0;
        #pragma unroll
        for (int w = 0; w < NWARP; w++) {
            r0 += s_red[w][0]; r1 += s_red[w][1];
            r2 += s_red[w][2]; r3 += s_red[w][3];
        }
        g_part[blockIdx.x] = make_float4(r0, r1, r2, r3);
    }

    // ── last-block finalize ──
    __threadfence();
    if (tid == 0) s_is_last = (atomicAdd(&g_count, 1) == NBLOCKS - 1) ? 1u : 0u;
    __syncthreads();
    if (!s_is_last) return;
    __threadfence();

    if (tid < 128) {
        int fimg = tid >> 4;        // 0..7 (8 imgs x 16 slots)
        int sub  = tid & 15;        // 0..15
        float w0 = 0, w1 = 0, w2 = 0, w3 = 0;
        for (int s = sub; s < NBLK_PER_IMG; s += 16) {
            float4 gv = g_part[fimg * NBLK_PER_IMG + s];
            w0 += gv.x; w1 += gv.y; w2 += gv.z; w3 += gv.w;
        }
        #pragma unroll
        for (int off = 8; off > 0; off >>= 1) {
            w0 += __shfl_down_sync(0xFFFFFFFFu, w0, off, 16);
            w1 += __shfl_down_sync(0xFFFFFFFFu, w1, off, 16);
            w2 += __shfl_down_sync(0xFFFFFFFFu, w2, off, 16);
            w3 += __shfl_down_sync(0xFFFFFFFFu, w3, off, 16);
        }
        if (sub == 0) {
            s_img[fimg][0] = w0; s_img[fimg][1] = w1;
            s_img[fimg][2] = w2; s_img[fimg][3] = w3;
        }
    }
    __syncthreads();
    if (tid == 0) {
        float obj_sum = 0, bbox_sum = 0, cls_sum = 0, num_pos = 0;
        #pragma unroll
        for (int i = 0; i < NIMG; i++) {
            float bces = s_img[i][0];
            float pc   = s_img[i][1];
            float bb   = s_img[i][2];
            float fls  = s_img[i][3];
            obj_sum  += bces * (1.0f * pc + 0.5f * ((float)NANCH - pc));
            bbox_sum += bb;
            cls_sum  += fls / fmaxf(pc * (float)NCLS, 1.0f);
            num_pos  += pc;
        }
        num_pos = fmaxf(num_pos, 1.0f);
        out[0] = obj_sum / (float)NIMG
               + 5.0f * bbox_sum / num_pos
               + cls_sum / (float)NIMG;
        g_count = 0;   // reset for next graph replay
    }
}

extern "C" void kernel_launch(void* const* d_in, const int* in_sizes, int n_in,
                              void* d_out, int out_size) {
    const float* obj   = (const float*)d_in[0];
    const float* boxes = (const float*)d_in[1];
    const float* cls   = (const float*)d_in[2];
    const float* tbox  = (const float*)d_in[3];
    const int*   tlab  = (const int*)d_in[4];
    float* out = (float*)d_out;

    loss_fused<<<NBLOCKS, THREADS>>>(obj, boxes, cls, tbox, tlab, out);
}

// round 16
// speedup vs baseline: 1.1000x; 1.1000x over previous
#include <cuda_runtime.h>

#define NANCH 19200      // 3*80*80 anchors per image
#define NIMG  8
#define MTGT  100
#define HALFM 50
#define NCLS  80
#define THREADS 256
#define NWARP (THREADS / 32)                // 8
#define SLOTS 128                           // anchor slots per block
#define APT 2
#define ANCH_PER_BLK (SLOTS * APT)          // 256
#define NBLK_PER_IMG (NANCH / ANCH_PER_BLK) // 75
#define NBLOCKS (NIMG * NBLK_PER_IMG)       // 600

#define LN2F   0.6931471805599453f
#define C_FALSE (0.75f * LN2F)

__device__ float4   g_part[NBLOCKS];
__device__ unsigned g_count;

__device__ __forceinline__ float frcp_approx(float x) {
    float r;
    asm("rcp.approx.f32 %0, %1;" : "=f"(r) : "f"(x));
    return r;
}

// non-target focal term / C_FALSE:  p^2 * lg2(Q),  Q=1+exp(x), p=1-rcp(Q)
__device__ __forceinline__ float false_core(float x) {
    float Q = 1.0f + __expf(x);
    float R = frcp_approx(Q);
    float L = __log2f(Q);
    float p = 1.0f - R;
    return p * p * L;
}

__device__ __forceinline__ float false4(float4 v) {
    return false_core(v.x) + false_core(v.y) + false_core(v.z) + false_core(v.w);
}

__global__ void __launch_bounds__(THREADS) loss_fused(
    const float* __restrict__ obj,    // [8,19200]
    const float* __restrict__ boxes,  // [8,19200,4] (cx,cy,w,h)
    const float* __restrict__ cls,    // [8,19200,80]
    const float* __restrict__ tbox,   // [8,100,4]
    const int*   __restrict__ tlab,   // [8,100]
    float*       __restrict__ out)
{
    __shared__ float4 s_lohi[MTGT];          // lox,loy,hix,hiy
    __shared__ float  s_area[MTGT];
    __shared__ int    s_lab[MTGT];
    __shared__ int    s_vm[2][SLOTS][APT];   // packed argmax per target-half
    __shared__ int    s_pos_rowb4[ANCH_PER_BLK]; // row*20 (float4 index)
    __shared__ int    s_pos_rt[ANCH_PER_BLK];    // (row<<7) | tgt
    __shared__ int    s_pos_lab[ANCH_PER_BLK];
    __shared__ int    s_wtot[4];
    __shared__ float  s_red[NWARP][4];
    __shared__ float  s_img[NIMG][4];
    __shared__ unsigned s_is_last;

    const int tid  = threadIdx.x;
    const int lane = tid & 31;
    const int wid  = tid >> 5;
    const int slot = tid & (SLOTS - 1);            // 0..127
    const int q    = tid >> 7;                     // target half 0..1
    const int img  = blockIdx.x / NBLK_PER_IMG;
    const int ablk = blockIdx.x % NBLK_PER_IMG;
    const int base = img * NANCH + ablk * ANCH_PER_BLK + slot * APT;

    // ── Targets to shared ──
    if (tid < MTGT) {
        float4 tb = ((const float4*)tbox)[img * MTGT + tid];
        s_lohi[tid] = make_float4(tb.x - 0.5f * tb.z, tb.y - 0.5f * tb.w,
                                  tb.x + 0.5f * tb.z, tb.y + 0.5f * tb.w);
        s_area[tid] = tb.z * tb.w;
        s_lab[tid]  = tlab[img * MTGT + tid];
    }
    __syncthreads();

    // ── Load this slot's 2 anchors ──
    float lo1x[APT], lo1y[APT], hi1x[APT], hi1y[APT], a1[APT];
    int   vmax[APT];
    #pragma unroll
    for (int a = 0; a < APT; a++) {
        float4 bxv = ((const float4*)boxes)[base + a];
        lo1x[a] = bxv.x - 0.5f * bxv.z;  lo1y[a] = bxv.y - 0.5f * bxv.w;
        hi1x[a] = bxv.x + 0.5f * bxv.z;  hi1y[a] = bxv.y + 0.5f * bxv.w;
        a1[a]   = bxv.z * bxv.w;
        vmax[a] = -1;
    }

    // ── Packed argmax of x = inter/(a1+ta) over this half's 50 targets ──
    const int m0 = q * HALFM;
    #pragma unroll 10
    for (int mm = 0; mm < HALFM; mm++) {
        int m = m0 + mm;
        float4 t  = s_lohi[m];
        float  ta = s_area[m];
        int idxbits = 127 - m;
        #pragma unroll
        for (int a = 0; a < APT; a++) {
            float wx = fminf(hi1x[a], t.z) - fmaxf(lo1x[a], t.x);    // unclamped
            float wy = fmaxf(fminf(hi1y[a], t.w) - fmaxf(lo1y[a], t.y), 0.0f);
            float inter = wx * wy;
            float x  = inter * frcp_approx(a1[a] + ta);
            int pk = (__float_as_int(x) & (int)0xFFFFFF80) | idxbits;
            vmax[a] = max(vmax[a], pk);
        }
    }
    s_vm[q][slot][0] = vmax[0];
    s_vm[q][slot][1] = vmax[1];
    __syncthreads();

    // ── Merge halves (threads 0..127), exact positivity, BCE ──
    float bce = 0.0f, posf = 0.0f;
    bool  pos0 = false, pos1 = false;
    int   b0 = 0, b1 = 0;
    if (tid < SLOTS) {
        #pragma unroll
        for (int a = 0; a < APT; a++) {
            int v = max(s_vm[0][slot][a], s_vm[1][slot][a]);
            int bidx = 127 - (v & 127);
            float4 t = s_lohi[bidx];
            float wx = fmaxf(fminf(hi1x[a], t.z) - fmaxf(lo1x[a], t.x), 0.0f);
            float wy = fmaxf(fminf(hi1y[a], t.w) - fmaxf(lo1y[a], t.y), 0.0f);
            bool p = (3.0f * (wx * wy) >= a1[a] + s_area[bidx] + 1e-6f);
            posf += p ? 1.0f : 0.0f;
            float o = obj[base + a];
            bce += -fmaxf(__logf(p ? o : 1.0f - o), -100.0f);
            if (a == 0) { pos0 = p; b0 = bidx; } else { pos1 = p; b1 = bidx; }
        }
    }

    // ── Deterministic compaction (anchor order); all threads reach syncs ──
    int c = (pos0 ? 1 : 0) + (pos1 ? 1 : 0);
    int pre = c;
    #pragma unroll
    for (int o = 1; o < 32; o <<= 1) {
        int n = __shfl_up_sync(0xFFFFFFFFu, pre, o);
        if (lane >= o) pre += n;
    }
    if (lane == 31 && wid < 4) s_wtot[wid] = pre;
    __syncthreads();
    const int P = s_wtot[0] + s_wtot[1] + s_wtot[2] + s_wtot[3];
    if (tid < SLOTS) {
        int wbase = 0;
        #pragma unroll
        for (int w = 0; w < 4; w++) wbase += (w < wid) ? s_wtot[w] : 0;
        int ofs = wbase + pre - c;
        if (pos0) {
            s_pos_rowb4[ofs] = base * (NCLS / 4);
            s_pos_rt[ofs]    = (base << 7) | b0;
            s_pos_lab[ofs]   = s_lab[b0];
            ofs++;
        }
        if (pos1) {
            s_pos_rowb4[ofs] = (base + 1) * (NCLS / 4);
            s_pos_rt[ofs]    = ((base + 1) << 7) | b1;
            s_pos_lab[ofs]   = s_lab[b1];
        }
    }
    __syncthreads();

    // ── Per-positive pass: GIoU + focal label-column correction (fused) ──
    float bbox = 0.0f;
    float fl = 0.0f;
    for (int i = tid; i < P; i += THREADS) {
        int rt = s_pos_rt[i];
        int prow = rt >> 7;
        int bm   = rt & 127;
        float4 pb = ((const float4*)boxes)[prow];   // L1-hot
        float plox = pb.x - 0.5f * pb.z, ploy = pb.y - 0.5f * pb.w;
        float phix = pb.x + 0.5f * pb.z, phiy = pb.y + 0.5f * pb.w;
        float pa   = pb.z * pb.w;
        float4 t = s_lohi[bm];
        float wx = fmaxf(fminf(phix, t.z) - fmaxf(plox, t.x), 0.0f);
        float wy = fmaxf(fminf(phiy, t.w) - fmaxf(ploy, t.y), 0.0f);
        float inter = wx * wy;
        float uni = pa + s_area[bm] - inter;
        float iou = __fdividef(inter, uni + 1e-6f);
        float ex = fmaxf(fmaxf(phix, t.z) - fminf(plox, t.x), 0.0f);
        float ey = fmaxf(fmaxf(phiy, t.w) - fminf(ploy, t.y), 0.0f);
        float enc = ex * ey;
        bbox += 1.0f - (iou - __fdividef(enc - uni, enc + 1e-6f));

        // label-column focal correction: + true_term − false_term
        float x = cls[s_pos_rowb4[i] * 4 + s_pos_lab[i]];
        float Q = 1.0f + __expf(x);
        float R = frcp_approx(Q);
        float L = __log2f(Q);
        float p = 1.0f - R;
        float falseT = C_FALSE * (p * p * L);
        float trueT  = 0.25f * (R * R) * (LN2F * L - x);
        fl += trueT - falseT;
    }

    // ── Focal main loop: float4-vectorized false formula over all 80 cols ──
    {
        const float4* cls4 = (const float4*)cls;
        const int items = P * (NCLS / 4);           // 20 vec-items per positive
        int i = tid;
        for (; i + THREADS < items; i += 2 * THREADS) {
            unsigned i0 = i, i1 = i + THREADS;
            unsigned a0 = i0 / 20u, a1i = i1 / 20u;
            int c0 = i0 - a0 * 20u, c1 = i1 - a1i * 20u;
            float4 v0 = cls4[s_pos_rowb4[a0] + c0];
            float4 v1 = cls4[s_pos_rowb4[a1i] + c1];
            fl = fmaf(false4(v0) + false4(v1), C_FALSE, fl);
        }
        if (i < items) {
            unsigned a = (unsigned)i / 20u;
            int cc = i - a * 20u;
            fl = fmaf(false4(cls4[s_pos_rowb4[a] + cc]), C_FALSE, fl);
        }
    }

    // ── single-sync fused block reduction of (bce, posf, bbox, fl) ──
    float v0 = bce, v1 = posf, v2 = bbox, v3 = fl;
    #pragma unroll
    for (int off = 16; off > 0; off >>= 1) {
        v0 += __shfl_down_sync(0xFFFFFFFFu, v0, off);
        v1 += __shfl_down_sync(0xFFFFFFFFu, v1, off);
        v2 += __shfl_down_sync(0xFFFFFFFFu, v2, off);
        v3 += __shfl_down_sync(0xFFFFFFFFu, v3, off);
    }
    if (lane == 0) {
        s_red[wid][0] = v0; s_red[wid][1] = v1;
        s_red[wid][2] = v2; s_red[wid][3] = v3;
    }
    __syncthreads();
    if (tid == 0) {
        float r0 = 0, r1 = 0, r2 = 0, r3 = 0;
        #pragma unroll
        for (int w = 0; w < NWARP; w++) {
            r0 += s_red[w][0]; r1 += s_red[w][1];
            r2 += s_red[w][2]; r3 += s_red[w][3];
        }
        g_part[blockIdx.x] = make_float4(r0, r1, r2, r3);
    }

    // ── last-block finalize ──
    __threadfence();
    if (tid == 0) s_is_last = (atomicAdd(&g_count, 1) == NBLOCKS - 1) ? 1u : 0u;
    __syncthreads();
    if (!s_is_last) return;
    __threadfence();

    if (tid < 128) {
        int fimg = tid >> 4;        // 0..7 (8 imgs x 16 slots)
        int sub  = tid & 15;        // 0..15
        float w0 = 0, w1 = 0, w2 = 0, w3 = 0;
        for (int s = sub; s < NBLK_PER_IMG; s += 16) {
            float4 gv = g_part[fimg * NBLK_PER_IMG + s];
            w0 += gv.x; w1 += gv.y; w2 += gv.z; w3 += gv.w;
        }
        #pragma unroll
        for (int off = 8; off > 0; off >>= 1) {
            w0 += __shfl_down_sync(0xFFFFFFFFu, w0, off, 16);
            w1 += __shfl_down_sync(0xFFFFFFFFu, w1, off, 16);
            w2 += __shfl_down_sync(0xFFFFFFFFu, w2, off, 16);
            w3 += __shfl_down_sync(0xFFFFFFFFu, w3, off, 16);
        }
        if (sub == 0) {
            s_img[fimg][0] = w0; s_img[fimg][1] = w1;
            s_img[fimg][2] = w2; s_img[fimg][3] = w3;
        }
    }
    __syncthreads();
    if (tid == 0) {
        float obj_sum = 0, bbox_sum = 0, cls_sum = 0, num_pos = 0;
        #pragma unroll
        for (int i = 0; i < NIMG; i++) {
            float bces = s_img[i][0];
            float pc   = s_img[i][1];
            float bb   = s_img[i][2];
            float fls  = s_img[i][3];
            obj_sum  += bces * (1.0f * pc + 0.5f * ((float)NANCH - pc));
            bbox_sum += bb;
            cls_sum  += fls / fmaxf(pc * (float)NCLS, 1.0f);
            num_pos  += pc;
        }
        num_pos = fmaxf(num_pos, 1.0f);
        out[0] = obj_sum / (float)NIMG
               + 5.0f * bbox_sum / num_pos
               + cls_sum / (float)NIMG;
        g_count = 0;   // reset for next graph replay
    }
}

extern "C" void kernel_launch(void* const* d_in, const int* in_sizes, int n_in,
                              void* d_out, int out_size) {
    const float* obj   = (const float*)d_in[0];
    const float* boxes = (const float*)d_in[1];
    const float* cls   = (const float*)d_in[2];
    const float* tbox  = (const float*)d_in[3];
    const int*   tlab  = (const int*)d_in[4];
    float* out = (float*)d_out;

    loss_fused<<<NBLOCKS, THREADS>>>(obj, boxes, cls, tbox, tlab, out);
}